// round 10
// baseline (speedup 1.0000x reference)
#include <cuda_runtime.h>
#include <cstdint>
#include <math.h>

#define VSZ 128
#define HW  (VSZ*VSZ)          // 16384
#define NB  4
#define NP  32
#define PE  16
#define NE  (NP*PE)            // 512 edges per batch
#define EPSF  1e-8f
#define BIGF  3.4e38f

// one edge step: distance + crossing. R={c1, ix_enc, vy, v0x}  E={ex,ey,exinv}
#define EDGE1(Rp, Ep, e, m2, cnt)                               \
    {                                                           \
        float4 R = (Rp)[e];                                     \
        float4 E = (Ep)[e];                                     \
        float tt = __saturatef(fmaf(px, E.z, R.x));             \
        float uu = px - R.w;                                    \
        float dx = fmaf(-E.x, tt, uu);                          \
        float dy = fmaf(-E.y, tt, R.z);                         \
        float d2 = fmaf(dy, dy, dx*dx);                         \
        m2 = fminf(m2, d2);                                     \
        cnt ^= (R.y > px) ? 1u : 0u;                            \
    }

// ---- single fused kernel: setup + SDF + mask + depth broadcast -------------
// 128 blocks x 512 threads, 1 block/SM. Each block redundantly compacts its
// batch's polygons from gmem (4KB, L2-broadcast), builds row-edge tables for
// its 4 rows directly in smem, runs a 4-way interleaved polygon loop, and
// depth-broadcasts via cp.async.bulk.
__global__ __launch_bounds__(512, 1) void mono_kernel(
    const float* __restrict__ polygons,
    const float* __restrict__ attributes,
    const float* __restrict__ validity,
    float* __restrict__ out)
{
    __shared__ float4 sRE[4*NE];            // {c1, ix_enc, vy, v0x}      32KB
    __shared__ float4 sEC[NE];              // {ex, ey, ex*inv, 0}         8KB
    __shared__ __align__(16) union {
        float2 shv[NP][PE];                 // vertices (phases 0-1)       4KB
        struct { float cmb[512]; float zero[512]; } tail;   // store phase
    } u;
    __shared__ int s_K[NP], s_slot[NP], s_act[NP];
    __shared__ int s_nact, s_hv;

    int b    = blockIdx.x >> 5;             // batch
    int tile = blockIdx.x & 31;             // 4-row tile within batch
    int t    = threadIdx.x;
    int w    = t >> 5;
    int l    = t & 31;
    const float hstep = 1.0f / (float)(VSZ - 1);

    // ---- phase 0: vertex compaction (16 warps x 2 polys) ----
    #pragma unroll
    for (int i = 0; i < 2; i++) {
        int n    = w*2 + i;
        int poly = b*NP + n;
        const float* pp = polygons + (size_t)poly * PE * 2;
        float x = 0.0f, y = 0.0f;
        bool valid = false;
        if (l < PE) {
            x = pp[2*l + 0];
            y = pp[2*l + 1];
            valid = (x + y) != 0.0f;
        }
        unsigned vm = __ballot_sync(0xffffffffu, valid);
        int K   = __popc(vm);
        int pos = __popc(vm & ((1u << l) - 1u));
        if (valid) u.shv[n][pos] = make_float2(x, y);
        if (l == 0) {
            s_K[n]   = K;
            s_act[n] = (K >= 3 && validity[poly] >= 0.5f) ? 1 : 0;
        }
    }
    __syncthreads();

    if (w == 0) {   // warp 0: compaction slots over the 32 poly flags
        int flag = s_act[l];
        unsigned am = __ballot_sync(0xffffffffu, flag != 0);
        int nact  = __popc(am);
        int below = __popc(am & ((1u << l) - 1u));
        s_slot[l] = flag ? below : (nact + (l - below));
        if (l == 0) {
            s_nact = nact;
            float av = fminf(fmaxf(attributes[b], 0.0f), 1.0f);
            int hv = (int)rintf(av * (float)VSZ);   // half-even, like jnp.rint
            s_hv = min(max(hv, 1), VSZ);
        }
    }
    __syncthreads();

    // ---- phase 1: row-edge tables, built from smem vertices (4 tasks/thr) --
    #pragma unroll
    for (int k = 0; k < 4; k++) {
        int i    = t + 512*k;
        int rr   = i >> 9;                  // row within block (k)
        int eidx = i & (NE - 1);
        int p    = eidx >> 4;               // source poly
        int e    = eidx & (PE - 1);
        int slot = s_slot[p];
        int K    = s_K[p];
        float4 R, E;
        if (s_act[p] && e < K) {
            float2 v0 = u.shv[p][e];
            float2 v1 = u.shv[p][(e + 1 == K) ? 0 : e + 1];
            float ex  = v1.x - v0.x;
            float ey  = v1.y - v0.y;
            float inv = 1.0f / (ex*ex + ey*ey + EPSF);
            float exinv = ex * inv, eyinv = ey * inv;
            float py  = (float)(tile*4 + rr) * hstep;
            float vy  = py - v0.y;
            bool  yc  = (v0.y <= py) != (v1.y <= py);
            float ix  = fmaf(ex / (ey + EPSF), vy, v0.x);
            float c1  = fmaf(-v0.x, exinv, vy * eyinv);
            R = make_float4(c1, yc ? ix : -BIGF, vy, v0.x);
            E = make_float4(ex, ey, exinv, 0.0f);
        } else {
            R = make_float4(0.0f, -BIGF, 1e30f, 0.0f);   // d2 -> inf, no cross
            E = make_float4(0.0f, 0.0f, 0.0f, 0.0f);
        }
        sRE[rr*NE + slot*PE + e] = R;
        if (rr == 0) sEC[slot*PE + e] = E;
    }
    __syncthreads();                         // vertices no longer needed

    u.tail.zero[t] = 0.0f;                   // safe: shv reads complete

    int   rr = t >> 7;
    float px = (float)(t & (VSZ-1)) * hstep;
    const float4* REr = sRE + rr * NE;

    // ---- phase 2: min over polys of signed d^2, 4 interleaved streams ------
    float S0 = BIGF, S1 = BIGF, S2 = BIGF, S3 = BIGF;
    int np4 = (s_nact + 3) >> 2;             // 4*np4-1 <= 31; sentinels safe
    for (int i = 0; i < np4; i++) {
        const float4* Rp0 = REr + (i          )*PE;
        const float4* Rp1 = REr + (i +   np4  )*PE;
        const float4* Rp2 = REr + (i + 2*np4  )*PE;
        const float4* Rp3 = REr + (i + 3*np4  )*PE;
        const float4* Ep0 = sEC + (i          )*PE;
        const float4* Ep1 = sEC + (i +   np4  )*PE;
        const float4* Ep2 = sEC + (i + 2*np4  )*PE;
        const float4* Ep3 = sEC + (i + 3*np4  )*PE;
        float m0 = BIGF, m1 = BIGF, m2v = BIGF, m3 = BIGF;
        unsigned c0 = 0u, c1u = 0u, c2 = 0u, c3 = 0u;
        #pragma unroll
        for (int e = 0; e < PE; e++) {
            EDGE1(Rp0, Ep0, e, m0,  c0);
            EDGE1(Rp1, Ep1, e, m1,  c1u);
            EDGE1(Rp2, Ep2, e, m2v, c2);
            EDGE1(Rp3, Ep3, e, m3,  c3);
        }
        S0 = fminf(S0, __uint_as_float(__float_as_uint(m0)  ^ (c0  << 31)));
        S1 = fminf(S1, __uint_as_float(__float_as_uint(m1)  ^ (c1u << 31)));
        S2 = fminf(S2, __uint_as_float(__float_as_uint(m2v) ^ (c2  << 31)));
        S3 = fminf(S3, __uint_as_float(__float_as_uint(m3)  ^ (c3  << 31)));
    }
    float S = fminf(fminf(S0, S1), fminf(S2, S3));

    float d   = sqrtf(fabsf(S));
    float sdf = (S < 0.0f) ? -d : d;
    float v   = __fdividef(1.0f, 1.0f + __expf(100.0f * sdf));

    // ---- phase 3: stage tile, depth-broadcast with async bulk copies -------
    u.tail.cmb[t] = v;
    __syncthreads();

    if (t < VSZ) {
        asm volatile("fence.proxy.async.shared::cta;" ::: "memory");
        int dz = t;                                  // depth slice
        const float* srcp = (dz < s_hv) ? u.tail.cmb : u.tail.zero;
        unsigned int saddr;
        asm("{ .reg .u64 a; cvta.to.shared.u64 a, %1; cvt.u32.u64 %0, a; }"
            : "=r"(saddr) : "l"(srcp));
        float* gdst = out + ((size_t)b * VSZ + dz) * HW + tile * 512;
        asm volatile("cp.async.bulk.global.shared::cta.bulk_group [%0], [%1], %2;"
                     :: "l"(gdst), "r"(saddr), "r"(512u * 4u) : "memory");
        asm volatile("cp.async.bulk.commit_group;" ::: "memory");
        asm volatile("cp.async.bulk.wait_group 0;" ::: "memory");
    }
}

// ---------------- launch ----------------------------------------------------
extern "C" void kernel_launch(void* const* d_in, const int* in_sizes, int n_in,
                              void* d_out, int out_size)
{
    const float* polygons   = (const float*)d_in[0];   // (4,32,16,2)
    const float* attributes = (const float*)d_in[1];   // (4,1)
    const float* validity   = (const float*)d_in[2];   // (4,32)
    float* out = (float*)d_out;                        // (4,128,128,128)

    mono_kernel<<<NB*32, 512>>>(polygons, attributes, validity, out);
}

// round 13
// speedup vs baseline: 1.0944x; 1.0944x over previous
#include <cuda_runtime.h>
#include <cstdint>
#include <math.h>

#define VSZ 128
#define HW  (VSZ*VSZ)          // 16384
#define NB  4
#define NP  32
#define PE  16
#define NE  (NP*PE)            // 512 edges per batch
#define EPSF  1e-8f
#define BIGF  3.4e38f

// ---------------- scratch (static device globals; no allocation) ------------
// per edge: A = {v0x, v0y, v1y, ex}; Bv = {ey, ex*inv, ey*inv, ex/(ey+eps)}
// polys compacted: active polys occupy slots [0,nact), sentinels after.
__device__ float4 g_edges[NB*NE*2];      // 64 KB
__device__ int    g_nact[NB];
__device__ int    g_hv[NB];

// ---------------- kernel A: setup + compaction (4 blocks x 256) -------------
__global__ __launch_bounds__(256) void setup_kernel(
    const float* __restrict__ polygons,
    const float* __restrict__ attributes,
    const float* __restrict__ validity)
{
    __shared__ float2 shv[NP][PE];
    __shared__ int    s_act[NP], s_K[NP], s_slot[NP];

    int w = threadIdx.x >> 5;     // warp 0..7, handles polys 4w..4w+3
    int l = threadIdx.x & 31;
    int b = blockIdx.x;

    #pragma unroll
    for (int i = 0; i < 4; i++) {
        int n = w*4 + i;
        int poly = b*NP + n;
        const float* pp = polygons + (size_t)poly * PE * 2;
        float x = 0.0f, y = 0.0f;
        bool valid = false;
        if (l < PE) {
            x = pp[2*l + 0];
            y = pp[2*l + 1];
            valid = (x + y) != 0.0f;
        }
        unsigned vm = __ballot_sync(0xffffffffu, valid);
        int K   = __popc(vm);
        int pos = __popc(vm & ((1u << l) - 1u));
        if (valid) shv[n][pos] = make_float2(x, y);
        if (l == 0) {
            s_K[n]   = K;
            s_act[n] = (K >= 3 && validity[poly] >= 0.5f) ? 1 : 0;
        }
    }
    __syncthreads();

    if (w == 0) {   // warp 0: compaction slots via ballot over 32 poly flags
        int flag = s_act[l];
        unsigned am = __ballot_sync(0xffffffffu, flag != 0);
        int nact  = __popc(am);
        int below = __popc(am & ((1u << l) - 1u));
        s_slot[l] = flag ? below : (nact + (l - below));
        if (l == 0) {
            g_nact[b] = nact;
            float av = attributes[b];                  // (B,1)
            av = fminf(fmaxf(av, 0.0f), 1.0f);
            int hv = (int)rintf(av * (float)VSZ);      // half-even, like jnp.rint
            g_hv[b] = min(max(hv, 1), VSZ);
        }
    }
    __syncthreads();

    #pragma unroll
    for (int i = 0; i < 4; i++) {
        int n = w*4 + i;
        int slot = s_slot[n];
        int K    = s_K[n];
        bool act = s_act[n] != 0;
        if (l < PE) {
            float4 A, Bv;
            if (act && l < K) {
                float2 v0 = shv[n][l];
                float2 v1 = shv[n][(l + 1 == K) ? 0 : l + 1];
                float ex = v1.x - v0.x;
                float ey = v1.y - v0.y;
                float inv = 1.0f / (ex*ex + ey*ey + EPSF);
                A  = make_float4(v0.x, v0.y, v1.y, ex);
                Bv = make_float4(ey, ex*inv, ey*inv, ex / (ey + EPSF));
            } else {
                A  = make_float4(0.0f, 1e30f, 1e30f, 0.0f);   // sentinel
                Bv = make_float4(0.0f, 0.0f, 0.0f, 0.0f);
            }
            size_t eidx = ((size_t)(b*NP + slot) * PE + l) * 2;
            g_edges[eidx + 0] = A;
            g_edges[eidx + 1] = Bv;
        }
    }
}

// one edge step: distance + crossing. R={c1, ix_enc, vy, v0x}  E={ex,ey,exinv}
#define EDGE1(Rp, Ep, e, m2, cnt)                               \
    {                                                           \
        float4 R = (Rp)[e];                                     \
        float4 E = (Ep)[e];                                     \
        float tt = __saturatef(fmaf(px, E.z, R.x));             \
        float uu = px - R.w;                                    \
        float dx = fmaf(-E.x, tt, uu);                          \
        float dy = fmaf(-E.y, tt, R.z);                         \
        float d2 = fmaf(dy, dy, dx*dx);                         \
        m2 = fminf(m2, d2);                                     \
        cnt ^= (R.y > px) ? 1u : 0u;                            \
    }

// ------- kernel B: fused SDF + mask + depth broadcast (256 x 512) -----------
// Block = 2-row x 128-px tile (256 pixels), 2 threads per pixel (polygon
// slots split even/odd between thread halves). 2 blocks co-resident per SM
// -> 32 warps/SM. Row-edge terms hoisted per (row, edge) into smem; depth
// broadcast via cp.async.bulk (1KB per depth slice).
__global__ __launch_bounds__(512, 2) void fused_kernel(float* __restrict__ out)
{
    __shared__ float4 sRE[2*NE];                   // {c1, ix_enc, vy, v0x}  16KB
    __shared__ float4 sEC[NE];                     // {ex, ey, ex*inv, 0}     8KB
    __shared__ float  s_S[512];                    // per-half signed d^2     2KB
    __shared__ __align__(16) float s_cmb[256];     // combined tile           1KB
    __shared__ __align__(16) float s_zero[256];    // zero tile               1KB
    __shared__ int    s_nact, s_hv;

    int b    = blockIdx.x >> 6;       // 64 tiles per batch
    int tile = blockIdx.x & 63;       // 2-row tile within batch
    int t    = threadIdx.x;

    const float hstep = 1.0f / (float)(VSZ - 1);
    const float4* ge = g_edges + (size_t)b * NE * 2;

    // ---- phase 1: row-edge table (1024 entries, 2 per thread) ----
    #pragma unroll
    for (int k = 0; k < 2; k++) {
        int i    = t + 512*k;
        int rr   = i >> 9;            // row within block (== k)
        int eidx = i & (NE - 1);
        float4 A  = ge[eidx*2 + 0];   // v0x, v0y, v1y, ex
        float4 Bv = ge[eidx*2 + 1];   // ey, ex*inv, ey*inv, ex/(ey+eps)
        float py  = (float)(tile*2 + rr) * hstep;
        float vy  = py - A.y;
        bool  yc  = (A.y <= py) != (A.z <= py);
        float ix  = fmaf(Bv.w, vy, A.x);
        float c1  = fmaf(-A.x, Bv.y, vy * Bv.z);   // t = px*(ex*inv) + c1
        sRE[i] = make_float4(c1, yc ? ix : -BIGF, vy, A.x);
        if (k == 0)                    // rr==0 here; also fill edge constants
            sEC[eidx] = make_float4(A.w, Bv.x, Bv.y, 0.0f);
    }
    if (t < 256) s_zero[t] = 0.0f;
    if (t == 0) { s_nact = g_nact[b]; s_hv = g_hv[b]; }
    __syncthreads();

    int   p    = t & 255;             // pixel within tile
    int   half = t >> 8;              // 0: even slots, 1: odd slots
    int   rr   = p >> 7;
    float px   = (float)(p & (VSZ-1)) * hstep;
    const float4* REr = sRE + rr * NE;

    // min over this half's polys of signed d^2 (monotone map of signed dist);
    // slots 2i+half for i<np2 cover [0, 2*np2) >= nact; sentinels -> +inf.
    float S = BIGF;
    int np2 = (s_nact + 1) >> 1;
    for (int i = 0; i < np2; i++) {
        int slot = 2*i + half;
        const float4* Rp = REr + slot*PE;
        const float4* Ep = sEC + slot*PE;
        float m2 = BIGF;
        unsigned cnt = 0u;
        #pragma unroll
        for (int e = 0; e < PE; e++) {
            EDGE1(Rp, Ep, e, m2, cnt);
        }
        S = fminf(S, __uint_as_float(__float_as_uint(m2) ^ (cnt << 31)));
    }
    s_S[t] = S;
    __syncthreads();

    // ---- combine halves, sigmoid, stage ----
    if (t < 256) {
        float Sm = fminf(s_S[t], s_S[t + 256]);
        float d   = sqrtf(fabsf(Sm));
        float sdf = (Sm < 0.0f) ? -d : d;
        s_cmb[t] = __fdividef(1.0f, 1.0f + __expf(100.0f * sdf));
    }
    __syncthreads();

    // ---- depth broadcast: 128 async bulk copies of 1KB ----
    if (t < VSZ) {
        asm volatile("fence.proxy.async.shared::cta;" ::: "memory");
        int dz = t;                                  // depth slice
        const float* srcp = (dz < s_hv) ? s_cmb : s_zero;
        unsigned int saddr;
        asm("{ .reg .u64 a; cvta.to.shared.u64 a, %1; cvt.u32.u64 %0, a; }"
            : "=r"(saddr) : "l"(srcp));
        float* gdst = out + ((size_t)b * VSZ + dz) * HW + tile * 256;
        asm volatile("cp.async.bulk.global.shared::cta.bulk_group [%0], [%1], %2;"
                     :: "l"(gdst), "r"(saddr), "r"(256u * 4u) : "memory");
        asm volatile("cp.async.bulk.commit_group;" ::: "memory");
        asm volatile("cp.async.bulk.wait_group 0;" ::: "memory");
    }
}

// ---------------- launch ----------------------------------------------------
extern "C" void kernel_launch(void* const* d_in, const int* in_sizes, int n_in,
                              void* d_out, int out_size)
{
    const float* polygons   = (const float*)d_in[0];   // (4,32,16,2)
    const float* attributes = (const float*)d_in[1];   // (4,1)
    const float* validity   = (const float*)d_in[2];   // (4,32)
    float* out = (float*)d_out;                        // (4,128,128,128)

    setup_kernel<<<NB, 256>>>(polygons, attributes, validity);
    fused_kernel<<<NB*64, 512>>>(out);
}